// round 12
// baseline (speedup 1.0000x reference)
#include <cuda_runtime.h>
#include <cstdint>

// Fixed problem sizes: N=100000 nodes, E=1600000 edges, d=128.
#define NMAX 100000
#define EMAX 1600000
#define D    128

// Scratch (device globals — no allocations allowed)
__device__ float g_dinv[NMAX];            // rsqrt(in_degree + 1)
__device__ int   g_deg[NMAX];             // in-degree (real edges only)
__device__ int   g_fill[NMAX];            // scatter fill counters (seeded = rowptr)
__device__ int   g_rowptr[NMAX + 1];      // CSR row pointers (by dst)
__device__ int   g_srcs[EMAX];            // CSR column indices (src of each edge)
__device__ int   g_bsum[1024];            // per-block degree sums for scan
__device__ float g_h[(size_t)NMAX * D];   // GEMM output (messages)
__device__ float g_a[(size_t)NMAX * D];   // aggregation output

// ---------------------------------------------------------------------------
// packed f32x2 helpers (sm_100+)
// ---------------------------------------------------------------------------
__device__ __forceinline__ unsigned long long pk2(float lo, float hi) {
    unsigned long long r;
    asm("mov.b64 %0, {%1,%2};" : "=l"(r) : "f"(lo), "f"(hi));
    return r;
}
__device__ __forceinline__ unsigned long long fma2(unsigned long long a,
                                                   unsigned long long b,
                                                   unsigned long long c) {
    unsigned long long d;
    asm("fma.rn.f32x2 %0, %1, %2, %3;" : "=l"(d) : "l"(a), "l"(b), "l"(c));
    return d;
}
__device__ __forceinline__ float2 upk2(unsigned long long v) {
    float2 f;
    asm("mov.b64 {%0,%1}, %2;" : "=f"(f.x), "=f"(f.y) : "l"(v));
    return f;
}

// ---------------------------------------------------------------------------
// CSR build
// ---------------------------------------------------------------------------
__global__ void zero_deg(int n) {
    int i = blockIdx.x * blockDim.x + threadIdx.x;
    if (i < n) g_deg[i] = 0;
}

// int4-vectorized degree histogram
__global__ void deg_hist(const int* __restrict__ dst, int e) {
    int i = (blockIdx.x * blockDim.x + threadIdx.x) * 4;
    if (i + 3 < e) {
        int4 d = *reinterpret_cast<const int4*>(dst + i);
        atomicAdd(&g_deg[d.x], 1);
        atomicAdd(&g_deg[d.y], 1);
        atomicAdd(&g_deg[d.z], 1);
        atomicAdd(&g_deg[d.w], 1);
    } else {
        for (; i < e; i++) atomicAdd(&g_deg[dst[i]], 1);
    }
}

// Phase 1: per-block degree sums (+ fused dinv). 256-thread blocks.
__global__ void scan_p1(int n) {
    int tid = threadIdx.x;
    int i = blockIdx.x * 256 + tid;
    int v = (i < n) ? g_deg[i] : 0;
    if (i < n) g_dinv[i] = rsqrtf((float)v + 1.0f);  // +1 self-loop
    int wsum = __reduce_add_sync(0xffffffffu, v);
    __shared__ int ws[8];
    if ((tid & 31) == 0) ws[tid >> 5] = wsum;
    __syncthreads();
    if (tid == 0) {
        int s = 0;
#pragma unroll
        for (int k = 0; k < 8; k++) s += ws[k];
        g_bsum[blockIdx.x] = s;
    }
}

// Phase 2: single 1024-thread block scans the (<=1024) block sums.
__global__ void scan_p2(int nb, int n) {
    __shared__ int ws[32];
    int tid = threadIdx.x;
    int v = (tid < nb) ? g_bsum[tid] : 0;
    int x = v;
#pragma unroll
    for (int o = 1; o < 32; o <<= 1) {
        int t = __shfl_up_sync(0xffffffffu, x, o);
        if ((tid & 31) >= o) x += t;
    }
    if ((tid & 31) == 31) ws[tid >> 5] = x;
    __syncthreads();
    if (tid < 32) {
        int y = ws[tid];
#pragma unroll
        for (int o = 1; o < 32; o <<= 1) {
            int t = __shfl_up_sync(0xffffffffu, y, o);
            if (tid >= o) y += t;
        }
        ws[tid] = y;
    }
    __syncthreads();
    int incl = x + ((tid >= 32) ? ws[(tid >> 5) - 1] : 0);
    if (tid < nb) g_bsum[tid] = incl - v;   // exclusive block offset
    if (tid == nb - 1) g_rowptr[n] = incl;  // total
}

// Phase 3: per-block exclusive scan + offset -> rowptr & fill seed.
__global__ void scan_p3(int n) {
    __shared__ int ws[8];
    int tid = threadIdx.x;
    int i = blockIdx.x * 256 + tid;
    int v = (i < n) ? g_deg[i] : 0;
    int lane = tid & 31, wid = tid >> 5;
    int x = v;
#pragma unroll
    for (int o = 1; o < 32; o <<= 1) {
        int t = __shfl_up_sync(0xffffffffu, x, o);
        if (lane >= o) x += t;
    }
    if (lane == 31) ws[wid] = x;
    __syncthreads();
    if (tid < 8) {
        int y = ws[tid];
#pragma unroll
        for (int o = 1; o < 8; o <<= 1) {
            int t = __shfl_up_sync(0xffu, y, o);
            if (tid >= o) y += t;
        }
        ws[tid] = y;
    }
    __syncthreads();
    int incl = x + (wid ? ws[wid - 1] : 0);
    if (i < n) {
        int excl = g_bsum[blockIdx.x] + incl - v;
        g_rowptr[i] = excl;
        g_fill[i]   = excl;
    }
}

// int4-vectorized scatter
__global__ void scatter_edges(const int* __restrict__ src, const int* __restrict__ dst, int e) {
    int i = (blockIdx.x * blockDim.x + threadIdx.x) * 4;
    if (i + 3 < e) {
        int4 d = *reinterpret_cast<const int4*>(dst + i);
        int4 s = *reinterpret_cast<const int4*>(src + i);
        g_srcs[atomicAdd(&g_fill[d.x], 1)] = s.x;
        g_srcs[atomicAdd(&g_fill[d.y], 1)] = s.y;
        g_srcs[atomicAdd(&g_fill[d.z], 1)] = s.z;
        g_srcs[atomicAdd(&g_fill[d.w], 1)] = s.w;
    } else {
        for (; i < e; i++) g_srcs[atomicAdd(&g_fill[dst[i]], 1)] = src[i];
    }
}

// ---------------------------------------------------------------------------
// GEMM: C[N,128] = A[N,128] @ W[128,128]   (packed f32x2; 16 rows/thread)
// 256 threads / 128 rows per block. W (64KB) + A tile (64KB) dynamic smem.
// Thread: lane -> 4 consecutive cols; tid>>5 -> row slot; 16 rows x 4 cols.
// W LDS loads amortize over 16 rows -> fma-bound, not LDS-bound.
// ---------------------------------------------------------------------------
__global__ void __launch_bounds__(256)
gemm128(const float* __restrict__ A, const float* __restrict__ W,
        float* __restrict__ C, int n) {
    extern __shared__ float sm[];
    float* sW = sm;              // 128*128
    float* sA = sm + 128 * 128;  // 128*128

    int tid = threadIdx.x;
    const float4* W4 = reinterpret_cast<const float4*>(W);
    float4* sW4 = reinterpret_cast<float4*>(sW);
#pragma unroll
    for (int i = 0; i < 16; i++) sW4[tid + 256 * i] = W4[tid + 256 * i];

    int row0 = blockIdx.x * 128;
    int nrows = n - row0; if (nrows > 128) nrows = 128;
    const float4* A4 = reinterpret_cast<const float4*>(A + (size_t)row0 * D);
    float4* sA4 = reinterpret_cast<float4*>(sA);
    for (int i = tid; i < nrows * 32; i += 256) sA4[i] = A4[i];
    __syncthreads();

    int lane = tid & 31;
    int rbase = tid >> 5;  // 0..7; thread rows = rbase + 8*r, r<16

    unsigned long long acc0[16], acc1[16];
#pragma unroll
    for (int r = 0; r < 16; r++) { acc0[r] = 0ull; acc1[r] = 0ull; }

#pragma unroll 2
    for (int k4 = 0; k4 < 32; k4++) {
        float4 w0 = sW4[(k4 * 4 + 0) * 32 + lane];
        float4 w1 = sW4[(k4 * 4 + 1) * 32 + lane];
        float4 w2 = sW4[(k4 * 4 + 2) * 32 + lane];
        float4 w3 = sW4[(k4 * 4 + 3) * 32 + lane];
        unsigned long long w0xy = pk2(w0.x, w0.y), w0zw = pk2(w0.z, w0.w);
        unsigned long long w1xy = pk2(w1.x, w1.y), w1zw = pk2(w1.z, w1.w);
        unsigned long long w2xy = pk2(w2.x, w2.y), w2zw = pk2(w2.z, w2.w);
        unsigned long long w3xy = pk2(w3.x, w3.y), w3zw = pk2(w3.z, w3.w);
#pragma unroll
        for (int r = 0; r < 16; r++) {
            float4 a = sA4[(rbase + r * 8) * 32 + k4];  // warp-uniform broadcast
            unsigned long long a0 = pk2(a.x, a.x);
            unsigned long long a1 = pk2(a.y, a.y);
            unsigned long long a2 = pk2(a.z, a.z);
            unsigned long long a3 = pk2(a.w, a.w);
            acc0[r] = fma2(a0, w0xy, acc0[r]); acc1[r] = fma2(a0, w0zw, acc1[r]);
            acc0[r] = fma2(a1, w1xy, acc0[r]); acc1[r] = fma2(a1, w1zw, acc1[r]);
            acc0[r] = fma2(a2, w2xy, acc0[r]); acc1[r] = fma2(a2, w2zw, acc1[r]);
            acc0[r] = fma2(a3, w3xy, acc0[r]); acc1[r] = fma2(a3, w3zw, acc1[r]);
        }
    }

    float4* C4 = reinterpret_cast<float4*>(C);
#pragma unroll
    for (int r = 0; r < 16; r++) {
        int rr = rbase + r * 8;
        if (rr < nrows) {
            float2 p0 = upk2(acc0[r]);
            float2 p1 = upk2(acc1[r]);
            float4 v; v.x = p0.x; v.y = p0.y; v.z = p1.x; v.w = p1.y;
            C4[(size_t)(row0 + rr) * 32 + lane] = v;
        }
    }
}

// ---------------------------------------------------------------------------
// CSR aggregation, fused epilogue:
//   a[v] = relu?( dinv[v] * sum_{s in N(v)} dinv[s]*h[s] + dinv[v]^2*h[v] + b )
// One warp per node; lane = one float4 of the 128-wide row.
// Indices staged cooperatively (coalesced load + shfl broadcast) so the
// 128B h-row gathers are independent -> high MLP, L2-throughput-bound.
// ---------------------------------------------------------------------------
__global__ void agg_csr(const float* __restrict__ bias, int n, int relu) {
    int v = (blockIdx.x * blockDim.x + threadIdx.x) >> 5;
    int lane = threadIdx.x & 31;
    if (v >= n) return;
    int beg = __ldg(&g_rowptr[v]);
    int end = __ldg(&g_rowptr[v + 1]);
    const float4* h4 = reinterpret_cast<const float4*>(g_h);

    float4 acc; acc.x = 0.f; acc.y = 0.f; acc.z = 0.f; acc.w = 0.f;
    for (int j0 = beg; j0 < end; j0 += 32) {
        int idx = j0 + lane;
        int s_l = 0; float w_l = 0.f;
        if (idx < end) {
            s_l = __ldg(&g_srcs[idx]);         // coalesced 32-wide
            w_l = __ldg(&g_dinv[s_l]);
        }
        int m = end - j0; if (m > 32) m = 32;
#pragma unroll 4
        for (int t = 0; t < m; t++) {
            int   s  = __shfl_sync(0xffffffffu, s_l, t);
            float ws = __shfl_sync(0xffffffffu, w_l, t);
            float4 hv = h4[(size_t)s * 32 + lane];   // independent gathers
            acc.x += ws * hv.x; acc.y += ws * hv.y;
            acc.z += ws * hv.z; acc.w += ws * hv.w;
        }
    }

    float dv = g_dinv[v];
    float ss = dv * dv;
    float4 hs = h4[(size_t)v * 32 + lane];
    float4 bb = reinterpret_cast<const float4*>(bias)[lane];
    acc.x = dv * acc.x + ss * hs.x + bb.x;
    acc.y = dv * acc.y + ss * hs.y + bb.y;
    acc.z = dv * acc.z + ss * hs.z + bb.z;
    acc.w = dv * acc.w + ss * hs.w + bb.w;
    if (relu) {
        acc.x = fmaxf(acc.x, 0.f); acc.y = fmaxf(acc.y, 0.f);
        acc.z = fmaxf(acc.z, 0.f); acc.w = fmaxf(acc.w, 0.f);
    }
    reinterpret_cast<float4*>(g_a)[(size_t)v * 32 + lane] = acc;
}

// ---------------------------------------------------------------------------
// Output GEMM: out[N,40] = g_a[N,128] @ Wout[128,40] + bout
// One thread per column-PAIR (f32x2): n*20 threads, fma2 inner loop.
// ---------------------------------------------------------------------------
__global__ void gemm_out(const float* __restrict__ W, const float* __restrict__ b,
                         float* __restrict__ C, int n) {
    __shared__ unsigned long long sW2[128 * 20];
    __shared__ float sb[40];
    int tid = threadIdx.x;
    for (int i = tid; i < 128 * 20; i += blockDim.x) {
        int k = i / 20, jp = i - k * 20;
        sW2[i] = pk2(W[k * 40 + jp * 2], W[k * 40 + jp * 2 + 1]);
    }
    if (tid < 40) sb[tid] = b[tid];
    __syncthreads();

    int idx = blockIdx.x * blockDim.x + tid;
    if (idx >= n * 20) return;
    int row = idx / 20;
    int jp = idx - row * 20;
    const float4* a4 = reinterpret_cast<const float4*>(g_a) + (size_t)row * 32;
    unsigned long long acc = pk2(sb[jp * 2], sb[jp * 2 + 1]);
#pragma unroll 8
    for (int k4 = 0; k4 < 32; k4++) {
        float4 av = a4[k4];
        int kb = k4 * 4;
        acc = fma2(pk2(av.x, av.x), sW2[(kb + 0) * 20 + jp], acc);
        acc = fma2(pk2(av.y, av.y), sW2[(kb + 1) * 20 + jp], acc);
        acc = fma2(pk2(av.z, av.z), sW2[(kb + 2) * 20 + jp], acc);
        acc = fma2(pk2(av.w, av.w), sW2[(kb + 3) * 20 + jp], acc);
    }
    float2 r = upk2(acc);
    reinterpret_cast<float2*>(C)[(size_t)row * 20 + jp] = r;
}

// ---------------------------------------------------------------------------
// launch
// ---------------------------------------------------------------------------
extern "C" void kernel_launch(void* const* d_in, const int* in_sizes, int n_in,
                              void* d_out, int out_size) {
    const float* x    = (const float*)d_in[0];
    const int*   ei   = (const int*)d_in[1];
    const float* W1   = (const float*)d_in[2];
    const float* b1   = (const float*)d_in[3];
    const float* W2   = (const float*)d_in[4];
    const float* b2   = (const float*)d_in[5];
    const float* Wout = (const float*)d_in[6];
    const float* bout = (const float*)d_in[7];
    float* out = (float*)d_out;

    int n = in_sizes[0] / D;   // 100000
    int e = in_sizes[1] / 2;   // 1600000
    const int* src = ei;
    const int* dst = ei + e;

    static bool attr_set = false;
    if (!attr_set) {
        cudaFuncSetAttribute(gemm128, cudaFuncAttributeMaxDynamicSharedMemorySize,
                             2 * 128 * 128 * (int)sizeof(float));
        attr_set = true;
    }
    const int smem_gemm = 2 * 128 * 128 * (int)sizeof(float);

    float* g_h_ptr; cudaGetSymbolAddress((void**)&g_h_ptr, g_h);
    float* g_a_ptr; cudaGetSymbolAddress((void**)&g_a_ptr, g_a);

    const int tb = 256;
    int nb_n  = (n + tb - 1) / tb;                 // 391
    int nb_e4 = ((e + 3) / 4 + tb - 1) / tb;       // vectorized edge blocks
    int gemm_blocks = (n + 127) / 128;
    int agg_blocks  = (n + 7) / 8;                 // 8 warps (nodes) per block

    // ---- CSR build + layer-1 GEMM interleaved ----
    zero_deg<<<nb_n, tb>>>(n);
    deg_hist<<<nb_e4, tb>>>(dst, e);
    scan_p1<<<nb_n, tb>>>(n);
    scan_p2<<<1, 1024>>>(nb_n, n);
    scan_p3<<<nb_n, tb>>>(n);
    gemm128<<<gemm_blocks, tb, smem_gemm>>>(x, W1, g_h_ptr, n);
    scatter_edges<<<nb_e4, tb>>>(src, dst, e);

    // ---- layer 1 aggregate: a = relu(Ahat h + b1) ----
    agg_csr<<<agg_blocks, tb>>>(b1, n, 1);

    // ---- layer 2 ----
    gemm128<<<gemm_blocks, tb, smem_gemm>>>(g_a_ptr, W2, g_h_ptr, n);
    agg_csr<<<agg_blocks, tb>>>(b2, n, 0);

    // ---- output: out = a@Wout + bout ----
    gemm_out<<<(n * 20 + tb - 1) / tb, tb>>>(Wout, bout, out, n);
}

// round 15
// speedup vs baseline: 1.0817x; 1.0817x over previous
#include <cuda_runtime.h>
#include <cstdint>

// Fixed problem sizes: N=100000 nodes, E=1600000 edges, d=128.
#define NMAX 100000
#define EMAX 1600000
#define D    128

// Scratch (device globals — no allocations allowed)
__device__ float g_dinv[NMAX];            // rsqrt(in_degree + 1)
__device__ int   g_deg[NMAX];             // in-degree (real edges only)
__device__ int   g_fill[NMAX];            // scatter fill counters (seeded = rowptr)
__device__ int   g_rowptr[NMAX + 1];      // CSR row pointers (by dst)
__device__ int   g_srcs[EMAX];            // CSR column indices (src of each edge)
__device__ int   g_bsum[1024];            // per-block degree sums for scan
__device__ float g_h[(size_t)NMAX * D];   // GEMM output (messages)
__device__ float g_a[(size_t)NMAX * D];   // aggregation output

// ---------------------------------------------------------------------------
// packed f32x2 helpers (sm_100+)
// ---------------------------------------------------------------------------
__device__ __forceinline__ unsigned long long pk2(float lo, float hi) {
    unsigned long long r;
    asm("mov.b64 %0, {%1,%2};" : "=l"(r) : "f"(lo), "f"(hi));
    return r;
}
__device__ __forceinline__ unsigned long long fma2(unsigned long long a,
                                                   unsigned long long b,
                                                   unsigned long long c) {
    unsigned long long d;
    asm("fma.rn.f32x2 %0, %1, %2, %3;" : "=l"(d) : "l"(a), "l"(b), "l"(c));
    return d;
}
__device__ __forceinline__ float2 upk2(unsigned long long v) {
    float2 f;
    asm("mov.b64 {%0,%1}, %2;" : "=f"(f.x), "=f"(f.y) : "l"(v));
    return f;
}

// ---------------------------------------------------------------------------
// CSR build
// ---------------------------------------------------------------------------
__global__ void zero_deg(int n) {
    int i = blockIdx.x * blockDim.x + threadIdx.x;
    if (i < n) g_deg[i] = 0;
}

// int4-vectorized degree histogram
__global__ void deg_hist(const int* __restrict__ dst, int e) {
    int i = (blockIdx.x * blockDim.x + threadIdx.x) * 4;
    if (i + 3 < e) {
        int4 d = *reinterpret_cast<const int4*>(dst + i);
        atomicAdd(&g_deg[d.x], 1);
        atomicAdd(&g_deg[d.y], 1);
        atomicAdd(&g_deg[d.z], 1);
        atomicAdd(&g_deg[d.w], 1);
    } else {
        for (; i < e; i++) atomicAdd(&g_deg[dst[i]], 1);
    }
}

// Phase 1: per-block degree sums (+ fused dinv). 256-thread blocks.
__global__ void scan_p1(int n) {
    int tid = threadIdx.x;
    int i = blockIdx.x * 256 + tid;
    int v = (i < n) ? g_deg[i] : 0;
    if (i < n) g_dinv[i] = rsqrtf((float)v + 1.0f);  // +1 self-loop
    int wsum = __reduce_add_sync(0xffffffffu, v);
    __shared__ int ws[8];
    if ((tid & 31) == 0) ws[tid >> 5] = wsum;
    __syncthreads();
    if (tid == 0) {
        int s = 0;
#pragma unroll
        for (int k = 0; k < 8; k++) s += ws[k];
        g_bsum[blockIdx.x] = s;
    }
}

// Phase 2: single 1024-thread block scans the (<=1024) block sums.
__global__ void scan_p2(int nb, int n) {
    __shared__ int ws[32];
    int tid = threadIdx.x;
    int v = (tid < nb) ? g_bsum[tid] : 0;
    int x = v;
#pragma unroll
    for (int o = 1; o < 32; o <<= 1) {
        int t = __shfl_up_sync(0xffffffffu, x, o);
        if ((tid & 31) >= o) x += t;
    }
    if ((tid & 31) == 31) ws[tid >> 5] = x;
    __syncthreads();
    if (tid < 32) {
        int y = ws[tid];
#pragma unroll
        for (int o = 1; o < 32; o <<= 1) {
            int t = __shfl_up_sync(0xffffffffu, y, o);
            if (tid >= o) y += t;
        }
        ws[tid] = y;
    }
    __syncthreads();
    int incl = x + ((tid >= 32) ? ws[(tid >> 5) - 1] : 0);
    if (tid < nb) g_bsum[tid] = incl - v;   // exclusive block offset
    if (tid == nb - 1) g_rowptr[n] = incl;  // total
}

// Phase 3: per-block exclusive scan + offset -> rowptr & fill seed.
__global__ void scan_p3(int n) {
    __shared__ int ws[8];
    int tid = threadIdx.x;
    int i = blockIdx.x * 256 + tid;
    int v = (i < n) ? g_deg[i] : 0;
    int lane = tid & 31, wid = tid >> 5;
    int x = v;
#pragma unroll
    for (int o = 1; o < 32; o <<= 1) {
        int t = __shfl_up_sync(0xffffffffu, x, o);
        if (lane >= o) x += t;
    }
    if (lane == 31) ws[wid] = x;
    __syncthreads();
    if (tid < 8) {
        int y = ws[tid];
#pragma unroll
        for (int o = 1; o < 8; o <<= 1) {
            int t = __shfl_up_sync(0xffu, y, o);
            if (tid >= o) y += t;
        }
        ws[tid] = y;
    }
    __syncthreads();
    int incl = x + (wid ? ws[wid - 1] : 0);
    if (i < n) {
        int excl = g_bsum[blockIdx.x] + incl - v;
        g_rowptr[i] = excl;
        g_fill[i]   = excl;
    }
}

// int4-vectorized scatter
__global__ void scatter_edges(const int* __restrict__ src, const int* __restrict__ dst, int e) {
    int i = (blockIdx.x * blockDim.x + threadIdx.x) * 4;
    if (i + 3 < e) {
        int4 d = *reinterpret_cast<const int4*>(dst + i);
        int4 s = *reinterpret_cast<const int4*>(src + i);
        g_srcs[atomicAdd(&g_fill[d.x], 1)] = s.x;
        g_srcs[atomicAdd(&g_fill[d.y], 1)] = s.y;
        g_srcs[atomicAdd(&g_fill[d.z], 1)] = s.z;
        g_srcs[atomicAdd(&g_fill[d.w], 1)] = s.w;
    } else {
        for (; i < e; i++) g_srcs[atomicAdd(&g_fill[dst[i]], 1)] = src[i];
    }
}

// ---------------------------------------------------------------------------
// GEMM: C[N,128] = A[N,128] @ W[128,128]   (packed f32x2; round-7 config)
// 256 threads / 64 rows per block. W (64KB) + A tile (32KB) dynamic smem
// = 96KB -> 2 blocks/SM. Thread: lane -> 4 cols; tid>>5 -> row slot;
// 8 rows x 4 cols. Measured 74us in round-7 profile.
// ---------------------------------------------------------------------------
__global__ void __launch_bounds__(256)
gemm128(const float* __restrict__ A, const float* __restrict__ W,
        float* __restrict__ C, int n) {
    extern __shared__ float sm[];
    float* sW = sm;             // 128*128
    float* sA = sm + 128 * 128; // 64*128

    int tid = threadIdx.x;
    const float4* W4 = reinterpret_cast<const float4*>(W);
    float4* sW4 = reinterpret_cast<float4*>(sW);
#pragma unroll
    for (int i = 0; i < 16; i++) sW4[tid + 256 * i] = W4[tid + 256 * i];

    int row0 = blockIdx.x * 64;
    int nrows = n - row0; if (nrows > 64) nrows = 64;
    const float4* A4 = reinterpret_cast<const float4*>(A + (size_t)row0 * D);
    float4* sA4 = reinterpret_cast<float4*>(sA);
    for (int i = tid; i < nrows * 32; i += 256) sA4[i] = A4[i];
    __syncthreads();

    int lane = tid & 31;
    int rbase = tid >> 5;  // 0..7

    unsigned long long acc0[8], acc1[8];
#pragma unroll
    for (int r = 0; r < 8; r++) { acc0[r] = 0ull; acc1[r] = 0ull; }

#pragma unroll 4
    for (int k4 = 0; k4 < 32; k4++) {
        float4 w0 = sW4[(k4 * 4 + 0) * 32 + lane];
        float4 w1 = sW4[(k4 * 4 + 1) * 32 + lane];
        float4 w2 = sW4[(k4 * 4 + 2) * 32 + lane];
        float4 w3 = sW4[(k4 * 4 + 3) * 32 + lane];
        unsigned long long w0xy = pk2(w0.x, w0.y), w0zw = pk2(w0.z, w0.w);
        unsigned long long w1xy = pk2(w1.x, w1.y), w1zw = pk2(w1.z, w1.w);
        unsigned long long w2xy = pk2(w2.x, w2.y), w2zw = pk2(w2.z, w2.w);
        unsigned long long w3xy = pk2(w3.x, w3.y), w3zw = pk2(w3.z, w3.w);
#pragma unroll
        for (int r = 0; r < 8; r++) {
            float4 a = sA4[(rbase + r * 8) * 32 + k4];  // warp-uniform broadcast
            unsigned long long a0 = pk2(a.x, a.x);
            unsigned long long a1 = pk2(a.y, a.y);
            unsigned long long a2 = pk2(a.z, a.z);
            unsigned long long a3 = pk2(a.w, a.w);
            acc0[r] = fma2(a0, w0xy, acc0[r]); acc1[r] = fma2(a0, w0zw, acc1[r]);
            acc0[r] = fma2(a1, w1xy, acc0[r]); acc1[r] = fma2(a1, w1zw, acc1[r]);
            acc0[r] = fma2(a2, w2xy, acc0[r]); acc1[r] = fma2(a2, w2zw, acc1[r]);
            acc0[r] = fma2(a3, w3xy, acc0[r]); acc1[r] = fma2(a3, w3zw, acc1[r]);
        }
    }

    float4* C4 = reinterpret_cast<float4*>(C);
#pragma unroll
    for (int r = 0; r < 8; r++) {
        int rr = rbase + r * 8;
        if (rr < nrows) {
            float2 p0 = upk2(acc0[r]);
            float2 p1 = upk2(acc1[r]);
            float4 v; v.x = p0.x; v.y = p0.y; v.z = p1.x; v.w = p1.y;
            C4[(size_t)(row0 + rr) * 32 + lane] = v;
        }
    }
}

// ---------------------------------------------------------------------------
// CSR aggregation, fused epilogue:
//   a[v] = relu?( dinv[v] * sum_{s in N(v)} dinv[s]*h[s] + dinv[v]^2*h[v] + b )
// One warp per node; lane = one float4 of the 128-wide row.
// Indices staged cooperatively (coalesced load + shfl broadcast) so the
// h-row gathers are independent -> high MLP, L2-throughput-bound.
// ---------------------------------------------------------------------------
__global__ void agg_csr(const float* __restrict__ bias, int n, int relu) {
    int v = (blockIdx.x * blockDim.x + threadIdx.x) >> 5;
    int lane = threadIdx.x & 31;
    if (v >= n) return;
    int beg = __ldg(&g_rowptr[v]);
    int end = __ldg(&g_rowptr[v + 1]);
    const float4* h4 = reinterpret_cast<const float4*>(g_h);

    float4 acc; acc.x = 0.f; acc.y = 0.f; acc.z = 0.f; acc.w = 0.f;
    for (int j0 = beg; j0 < end; j0 += 32) {
        int idx = j0 + lane;
        int s_l = 0; float w_l = 0.f;
        if (idx < end) {
            s_l = __ldg(&g_srcs[idx]);         // coalesced 32-wide
            w_l = __ldg(&g_dinv[s_l]);
        }
        int m = end - j0; if (m > 32) m = 32;
#pragma unroll 4
        for (int t = 0; t < m; t++) {
            int   s  = __shfl_sync(0xffffffffu, s_l, t);
            float ws = __shfl_sync(0xffffffffu, w_l, t);
            float4 hv = h4[(size_t)s * 32 + lane];   // independent gathers
            acc.x += ws * hv.x; acc.y += ws * hv.y;
            acc.z += ws * hv.z; acc.w += ws * hv.w;
        }
    }

    float dv = g_dinv[v];
    float ss = dv * dv;
    float4 hs = h4[(size_t)v * 32 + lane];
    float4 bb = reinterpret_cast<const float4*>(bias)[lane];
    acc.x = dv * acc.x + ss * hs.x + bb.x;
    acc.y = dv * acc.y + ss * hs.y + bb.y;
    acc.z = dv * acc.z + ss * hs.z + bb.z;
    acc.w = dv * acc.w + ss * hs.w + bb.w;
    if (relu) {
        acc.x = fmaxf(acc.x, 0.f); acc.y = fmaxf(acc.y, 0.f);
        acc.z = fmaxf(acc.z, 0.f); acc.w = fmaxf(acc.w, 0.f);
    }
    reinterpret_cast<float4*>(g_a)[(size_t)v * 32 + lane] = acc;
}

// ---------------------------------------------------------------------------
// Output GEMM: out[N,40] = g_a[N,128] @ Wout[128,40] + bout
// One thread per column-PAIR (f32x2): n*20 threads, fma2 inner loop.
// ---------------------------------------------------------------------------
__global__ void gemm_out(const float* __restrict__ W, const float* __restrict__ b,
                         float* __restrict__ C, int n) {
    __shared__ unsigned long long sW2[128 * 20];
    __shared__ float sb[40];
    int tid = threadIdx.x;
    for (int i = tid; i < 128 * 20; i += blockDim.x) {
        int k = i / 20, jp = i - k * 20;
        sW2[i] = pk2(W[k * 40 + jp * 2], W[k * 40 + jp * 2 + 1]);
    }
    if (tid < 40) sb[tid] = b[tid];
    __syncthreads();

    int idx = blockIdx.x * blockDim.x + tid;
    if (idx >= n * 20) return;
    int row = idx / 20;
    int jp = idx - row * 20;
    const float4* a4 = reinterpret_cast<const float4*>(g_a) + (size_t)row * 32;
    unsigned long long acc = pk2(sb[jp * 2], sb[jp * 2 + 1]);
#pragma unroll 8
    for (int k4 = 0; k4 < 32; k4++) {
        float4 av = a4[k4];
        int kb = k4 * 4;
        acc = fma2(pk2(av.x, av.x), sW2[(kb + 0) * 20 + jp], acc);
        acc = fma2(pk2(av.y, av.y), sW2[(kb + 1) * 20 + jp], acc);
        acc = fma2(pk2(av.z, av.z), sW2[(kb + 2) * 20 + jp], acc);
        acc = fma2(pk2(av.w, av.w), sW2[(kb + 3) * 20 + jp], acc);
    }
    float2 r = upk2(acc);
    reinterpret_cast<float2*>(C)[(size_t)row * 20 + jp] = r;
}

// ---------------------------------------------------------------------------
// launch   (gemm128 hoisted to slot 4 — ncu captures launch #4; gemm has no
//           dependency on the scan so it can sit between scan_p1 and scan_p2)
// ---------------------------------------------------------------------------
extern "C" void kernel_launch(void* const* d_in, const int* in_sizes, int n_in,
                              void* d_out, int out_size) {
    const float* x    = (const float*)d_in[0];
    const int*   ei   = (const int*)d_in[1];
    const float* W1   = (const float*)d_in[2];
    const float* b1   = (const float*)d_in[3];
    const float* W2   = (const float*)d_in[4];
    const float* b2   = (const float*)d_in[5];
    const float* Wout = (const float*)d_in[6];
    const float* bout = (const float*)d_in[7];
    float* out = (float*)d_out;

    int n = in_sizes[0] / D;   // 100000
    int e = in_sizes[1] / 2;   // 1600000
    const int* src = ei;
    const int* dst = ei + e;

    static bool attr_set = false;
    if (!attr_set) {
        cudaFuncSetAttribute(gemm128, cudaFuncAttributeMaxDynamicSharedMemorySize,
                             (128 * 128 + 64 * 128) * (int)sizeof(float));
        attr_set = true;
    }
    const int smem_gemm = (128 * 128 + 64 * 128) * (int)sizeof(float);

    float* g_h_ptr; cudaGetSymbolAddress((void**)&g_h_ptr, g_h);
    float* g_a_ptr; cudaGetSymbolAddress((void**)&g_a_ptr, g_a);

    const int tb = 256;
    int nb_n  = (n + tb - 1) / tb;                 // 391
    int nb_e4 = ((e + 3) / 4 + tb - 1) / tb;       // vectorized edge blocks
    int gemm_blocks = (n + 63) / 64;
    int agg_blocks  = (n + 7) / 8;                 // 8 warps (nodes) per block

    // ---- CSR build + layer-1 GEMM interleaved ----
    zero_deg<<<nb_n, tb>>>(n);                                    // 1
    deg_hist<<<nb_e4, tb>>>(dst, e);                              // 2
    scan_p1<<<nb_n, tb>>>(n);                                     // 3
    gemm128<<<gemm_blocks, tb, smem_gemm>>>(x, W1, g_h_ptr, n);   // 4 <- profiled
    scan_p2<<<1, 1024>>>(nb_n, n);                                // 5
    scan_p3<<<nb_n, tb>>>(n);                                     // 6
    scatter_edges<<<nb_e4, tb>>>(src, dst, e);                    // 7

    // ---- layer 1 aggregate: a = relu(Ahat h + b1) ----
    agg_csr<<<agg_blocks, tb>>>(b1, n, 1);                        // 8

    // ---- layer 2 ----
    gemm128<<<gemm_blocks, tb, smem_gemm>>>(g_a_ptr, W2, g_h_ptr, n);
    agg_csr<<<agg_blocks, tb>>>(b2, n, 0);

    // ---- output: out = a@Wout + bout ----
    gemm_out<<<(n * 20 + tb - 1) / tb, tb>>>(Wout, bout, out, n);
}

// round 16
// speedup vs baseline: 1.6100x; 1.4883x over previous
#include <cuda_runtime.h>
#include <cstdint>

// Fixed problem sizes: N=100000 nodes, E=1600000 edges, d=128.
#define NMAX 100000
#define EMAX 1600000
#define D    128

// Scratch (device globals — no allocations allowed)
__device__ float g_dinv[NMAX];            // rsqrt(in_degree + 1)
__device__ int   g_deg[NMAX];             // in-degree (real edges only)
__device__ int   g_fill[NMAX];            // scatter fill counters (seeded = rowptr)
__device__ int   g_rowptr[NMAX + 1];      // CSR row pointers (by dst)
__device__ int   g_srcs[EMAX];            // CSR column indices (src of each edge)
__device__ int   g_bsum[1024];            // per-block degree sums for scan
__device__ float g_h[(size_t)NMAX * D];   // GEMM output (messages)
__device__ float g_a[(size_t)NMAX * D];   // aggregation output

// ---------------------------------------------------------------------------
// packed f32x2 helpers (sm_100+)
// ---------------------------------------------------------------------------
__device__ __forceinline__ unsigned long long pk2(float lo, float hi) {
    unsigned long long r;
    asm("mov.b64 %0, {%1,%2};" : "=l"(r) : "f"(lo), "f"(hi));
    return r;
}
__device__ __forceinline__ unsigned long long fma2(unsigned long long a,
                                                   unsigned long long b,
                                                   unsigned long long c) {
    unsigned long long d;
    asm("fma.rn.f32x2 %0, %1, %2, %3;" : "=l"(d) : "l"(a), "l"(b), "l"(c));
    return d;
}
__device__ __forceinline__ float2 upk2(unsigned long long v) {
    float2 f;
    asm("mov.b64 {%0,%1}, %2;" : "=f"(f.x), "=f"(f.y) : "l"(v));
    return f;
}

// ---------------------------------------------------------------------------
// CSR build
// ---------------------------------------------------------------------------
__global__ void zero_deg(int n) {
    int i = blockIdx.x * blockDim.x + threadIdx.x;
    if (i < n) g_deg[i] = 0;
}

// int4-vectorized degree histogram
__global__ void deg_hist(const int* __restrict__ dst, int e) {
    int i = (blockIdx.x * blockDim.x + threadIdx.x) * 4;
    if (i + 3 < e) {
        int4 d = *reinterpret_cast<const int4*>(dst + i);
        atomicAdd(&g_deg[d.x], 1);
        atomicAdd(&g_deg[d.y], 1);
        atomicAdd(&g_deg[d.z], 1);
        atomicAdd(&g_deg[d.w], 1);
    } else {
        for (; i < e; i++) atomicAdd(&g_deg[dst[i]], 1);
    }
}

// Phase 1: per-block degree sums (+ fused dinv). 256-thread blocks.
__global__ void scan_p1(int n) {
    int tid = threadIdx.x;
    int i = blockIdx.x * 256 + tid;
    int v = (i < n) ? g_deg[i] : 0;
    if (i < n) g_dinv[i] = rsqrtf((float)v + 1.0f);  // +1 self-loop
    int wsum = __reduce_add_sync(0xffffffffu, v);
    __shared__ int ws[8];
    if ((tid & 31) == 0) ws[tid >> 5] = wsum;
    __syncthreads();
    if (tid == 0) {
        int s = 0;
#pragma unroll
        for (int k = 0; k < 8; k++) s += ws[k];
        g_bsum[blockIdx.x] = s;
    }
}

// Phase 2: single 1024-thread block scans the (<=1024) block sums.
__global__ void scan_p2(int nb, int n) {
    __shared__ int ws[32];
    int tid = threadIdx.x;
    int v = (tid < nb) ? g_bsum[tid] : 0;
    int x = v;
#pragma unroll
    for (int o = 1; o < 32; o <<= 1) {
        int t = __shfl_up_sync(0xffffffffu, x, o);
        if ((tid & 31) >= o) x += t;
    }
    if ((tid & 31) == 31) ws[tid >> 5] = x;
    __syncthreads();
    if (tid < 32) {
        int y = ws[tid];
#pragma unroll
        for (int o = 1; o < 32; o <<= 1) {
            int t = __shfl_up_sync(0xffffffffu, y, o);
            if (tid >= o) y += t;
        }
        ws[tid] = y;
    }
    __syncthreads();
    int incl = x + ((tid >= 32) ? ws[(tid >> 5) - 1] : 0);
    if (tid < nb) g_bsum[tid] = incl - v;   // exclusive block offset
    if (tid == nb - 1) g_rowptr[n] = incl;  // total
}

// Phase 3: per-block exclusive scan + offset -> rowptr & fill seed.
__global__ void scan_p3(int n) {
    __shared__ int ws[8];
    int tid = threadIdx.x;
    int i = blockIdx.x * 256 + tid;
    int v = (i < n) ? g_deg[i] : 0;
    int lane = tid & 31, wid = tid >> 5;
    int x = v;
#pragma unroll
    for (int o = 1; o < 32; o <<= 1) {
        int t = __shfl_up_sync(0xffffffffu, x, o);
        if (lane >= o) x += t;
    }
    if (lane == 31) ws[wid] = x;
    __syncthreads();
    if (tid < 8) {
        int y = ws[tid];
#pragma unroll
        for (int o = 1; o < 8; o <<= 1) {
            int t = __shfl_up_sync(0xffu, y, o);
            if (tid >= o) y += t;
        }
        ws[tid] = y;
    }
    __syncthreads();
    int incl = x + (wid ? ws[wid - 1] : 0);
    if (i < n) {
        int excl = g_bsum[blockIdx.x] + incl - v;
        g_rowptr[i] = excl;
        g_fill[i]   = excl;
    }
}

// int4-vectorized scatter
__global__ void scatter_edges(const int* __restrict__ src, const int* __restrict__ dst, int e) {
    int i = (blockIdx.x * blockDim.x + threadIdx.x) * 4;
    if (i + 3 < e) {
        int4 d = *reinterpret_cast<const int4*>(dst + i);
        int4 s = *reinterpret_cast<const int4*>(src + i);
        g_srcs[atomicAdd(&g_fill[d.x], 1)] = s.x;
        g_srcs[atomicAdd(&g_fill[d.y], 1)] = s.y;
        g_srcs[atomicAdd(&g_fill[d.z], 1)] = s.z;
        g_srcs[atomicAdd(&g_fill[d.w], 1)] = s.w;
    } else {
        for (; i < e; i++) g_srcs[atomicAdd(&g_fill[dst[i]], 1)] = src[i];
    }
}

// ---------------------------------------------------------------------------
// GEMM: C[N,128] = A[N,128] @ W[128,128]
// EXACT round-6 configuration (measured 74us, regs=76 in round-7 profile):
// 256 threads / 64 rows per block; W (64KB) + A (32KB) dynamic smem = 96KB
// -> 2 blocks/SM. Per-k: one W float4 (lane-strided) + scalar A broadcast.
// ---------------------------------------------------------------------------
__global__ void gemm128(const float* __restrict__ A, const float* __restrict__ W,
                        float* __restrict__ C, int n) {
    extern __shared__ float sm[];
    float* sW = sm;             // 128*128
    float* sA = sm + 128 * 128; // 64*128

    int tid = threadIdx.x;
    const float4* W4 = reinterpret_cast<const float4*>(W);
    float4* sW4 = reinterpret_cast<float4*>(sW);
#pragma unroll
    for (int i = 0; i < 16; i++) sW4[tid + 256 * i] = W4[tid + 256 * i];

    int row0 = blockIdx.x * 64;
    int nrows = n - row0; if (nrows > 64) nrows = 64;
    const float4* A4 = reinterpret_cast<const float4*>(A + (size_t)row0 * D);
    float4* sA4 = reinterpret_cast<float4*>(sA);
    for (int i = tid; i < nrows * 32; i += 256) sA4[i] = A4[i];
    __syncthreads();

    int lane = tid & 31;
    int rbase = tid >> 5;  // 0..7

    unsigned long long acc0[8], acc1[8];
#pragma unroll
    for (int r = 0; r < 8; r++) { acc0[r] = 0ull; acc1[r] = 0ull; }

#pragma unroll 4
    for (int k = 0; k < 128; k++) {
        float4 w = sW4[k * 32 + lane];
        unsigned long long wxy = pk2(w.x, w.y);
        unsigned long long wzw = pk2(w.z, w.w);
#pragma unroll
        for (int r = 0; r < 8; r++) {
            float a = sA[(rbase + r * 8) * 128 + k];  // warp-uniform broadcast
            unsigned long long aa = pk2(a, a);
            acc0[r] = fma2(aa, wxy, acc0[r]);
            acc1[r] = fma2(aa, wzw, acc1[r]);
        }
    }

    float4* C4 = reinterpret_cast<float4*>(C);
#pragma unroll
    for (int r = 0; r < 8; r++) {
        int rr = rbase + r * 8;
        if (rr < nrows) {
            float2 p0 = upk2(acc0[r]);
            float2 p1 = upk2(acc1[r]);
            float4 v; v.x = p0.x; v.y = p0.y; v.z = p1.x; v.w = p1.y;
            C4[(size_t)(row0 + rr) * 32 + lane] = v;
        }
    }
}

// ---------------------------------------------------------------------------
// CSR aggregation, fused epilogue:
//   a[v] = relu?( dinv[v] * sum_{s in N(v)} dinv[s]*h[s] + dinv[v]^2*h[v] + b )
// One warp per node; lane = one float4 of the 128-wide row.
// Indices staged cooperatively (coalesced load + shfl broadcast) so the
// h-row gathers are independent -> high MLP, L2-throughput-bound.
// ---------------------------------------------------------------------------
__global__ void agg_csr(const float* __restrict__ bias, int n, int relu) {
    int v = (blockIdx.x * blockDim.x + threadIdx.x) >> 5;
    int lane = threadIdx.x & 31;
    if (v >= n) return;
    int beg = __ldg(&g_rowptr[v]);
    int end = __ldg(&g_rowptr[v + 1]);
    const float4* h4 = reinterpret_cast<const float4*>(g_h);

    float4 acc; acc.x = 0.f; acc.y = 0.f; acc.z = 0.f; acc.w = 0.f;
    for (int j0 = beg; j0 < end; j0 += 32) {
        int idx = j0 + lane;
        int s_l = 0; float w_l = 0.f;
        if (idx < end) {
            s_l = __ldg(&g_srcs[idx]);         // coalesced 32-wide
            w_l = __ldg(&g_dinv[s_l]);
        }
        int m = end - j0; if (m > 32) m = 32;
#pragma unroll 4
        for (int t = 0; t < m; t++) {
            int   s  = __shfl_sync(0xffffffffu, s_l, t);
            float ws = __shfl_sync(0xffffffffu, w_l, t);
            float4 hv = h4[(size_t)s * 32 + lane];   // independent gathers
            acc.x += ws * hv.x; acc.y += ws * hv.y;
            acc.z += ws * hv.z; acc.w += ws * hv.w;
        }
    }

    float dv = g_dinv[v];
    float ss = dv * dv;
    float4 hs = h4[(size_t)v * 32 + lane];
    float4 bb = reinterpret_cast<const float4*>(bias)[lane];
    acc.x = dv * acc.x + ss * hs.x + bb.x;
    acc.y = dv * acc.y + ss * hs.y + bb.y;
    acc.z = dv * acc.z + ss * hs.z + bb.z;
    acc.w = dv * acc.w + ss * hs.w + bb.w;
    if (relu) {
        acc.x = fmaxf(acc.x, 0.f); acc.y = fmaxf(acc.y, 0.f);
        acc.z = fmaxf(acc.z, 0.f); acc.w = fmaxf(acc.w, 0.f);
    }
    reinterpret_cast<float4*>(g_a)[(size_t)v * 32 + lane] = acc;
}

// ---------------------------------------------------------------------------
// Output GEMM: out[N,40] = g_a[N,128] @ Wout[128,40] + bout
// One thread per column-PAIR (f32x2): n*20 threads, fma2 inner loop.
// ---------------------------------------------------------------------------
__global__ void gemm_out(const float* __restrict__ W, const float* __restrict__ b,
                         float* __restrict__ C, int n) {
    __shared__ unsigned long long sW2[128 * 20];
    __shared__ float sb[40];
    int tid = threadIdx.x;
    for (int i = tid; i < 128 * 20; i += blockDim.x) {
        int k = i / 20, jp = i - k * 20;
        sW2[i] = pk2(W[k * 40 + jp * 2], W[k * 40 + jp * 2 + 1]);
    }
    if (tid < 40) sb[tid] = b[tid];
    __syncthreads();

    int idx = blockIdx.x * blockDim.x + tid;
    if (idx >= n * 20) return;
    int row = idx / 20;
    int jp = idx - row * 20;
    const float4* a4 = reinterpret_cast<const float4*>(g_a) + (size_t)row * 32;
    unsigned long long acc = pk2(sb[jp * 2], sb[jp * 2 + 1]);
#pragma unroll 8
    for (int k4 = 0; k4 < 32; k4++) {
        float4 av = a4[k4];
        int kb = k4 * 4;
        acc = fma2(pk2(av.x, av.x), sW2[(kb + 0) * 20 + jp], acc);
        acc = fma2(pk2(av.y, av.y), sW2[(kb + 1) * 20 + jp], acc);
        acc = fma2(pk2(av.z, av.z), sW2[(kb + 2) * 20 + jp], acc);
        acc = fma2(pk2(av.w, av.w), sW2[(kb + 3) * 20 + jp], acc);
    }
    float2 r = upk2(acc);
    reinterpret_cast<float2*>(C)[(size_t)row * 20 + jp] = r;
}

// ---------------------------------------------------------------------------
// launch   (gemm128 in slot 4 — ncu captures launch #4; gemm has no
//           dependency on the scan so it sits between scan_p1 and scan_p2)
// ---------------------------------------------------------------------------
extern "C" void kernel_launch(void* const* d_in, const int* in_sizes, int n_in,
                              void* d_out, int out_size) {
    const float* x    = (const float*)d_in[0];
    const int*   ei   = (const int*)d_in[1];
    const float* W1   = (const float*)d_in[2];
    const float* b1   = (const float*)d_in[3];
    const float* W2   = (const float*)d_in[4];
    const float* b2   = (const float*)d_in[5];
    const float* Wout = (const float*)d_in[6];
    const float* bout = (const float*)d_in[7];
    float* out = (float*)d_out;

    int n = in_sizes[0] / D;   // 100000
    int e = in_sizes[1] / 2;   // 1600000
    const int* src = ei;
    const int* dst = ei + e;

    static bool attr_set = false;
    if (!attr_set) {
        cudaFuncSetAttribute(gemm128, cudaFuncAttributeMaxDynamicSharedMemorySize,
                             (128 * 128 + 64 * 128) * (int)sizeof(float));
        attr_set = true;
    }
    const int smem_gemm = (128 * 128 + 64 * 128) * (int)sizeof(float);

    float* g_h_ptr; cudaGetSymbolAddress((void**)&g_h_ptr, g_h);
    float* g_a_ptr; cudaGetSymbolAddress((void**)&g_a_ptr, g_a);

    const int tb = 256;
    int nb_n  = (n + tb - 1) / tb;                 // 391
    int nb_e4 = ((e + 3) / 4 + tb - 1) / tb;       // vectorized edge blocks
    int gemm_blocks = (n + 63) / 64;
    int agg_blocks  = (n + 7) / 8;                 // 8 warps (nodes) per block

    // ---- CSR build + layer-1 GEMM interleaved ----
    zero_deg<<<nb_n, tb>>>(n);                                    // 1
    deg_hist<<<nb_e4, tb>>>(dst, e);                              // 2
    scan_p1<<<nb_n, tb>>>(n);                                     // 3
    gemm128<<<gemm_blocks, tb, smem_gemm>>>(x, W1, g_h_ptr, n);   // 4 <- profiled
    scan_p2<<<1, 1024>>>(nb_n, n);                                // 5
    scan_p3<<<nb_n, tb>>>(n);                                     // 6
    scatter_edges<<<nb_e4, tb>>>(src, dst, e);                    // 7

    // ---- layer 1 aggregate: a = relu(Ahat h + b1) ----
    agg_csr<<<agg_blocks, tb>>>(b1, n, 1);                        // 8

    // ---- layer 2 ----
    gemm128<<<gemm_blocks, tb, smem_gemm>>>(g_a_ptr, W2, g_h_ptr, n);
    agg_csr<<<agg_blocks, tb>>>(b2, n, 0);

    // ---- output: out = a@Wout + bout ----
    gemm_out<<<(n * 20 + tb - 1) / tb, tb>>>(Wout, bout, out, n);
}